// round 5
// baseline (speedup 1.0000x reference)
#include <cuda_runtime.h>
#include <math.h>

#define NBATCH 16

typedef unsigned long long u64;

// ---------------- f32x2 helpers ----------------
__device__ __forceinline__ void fma2(u64 &acc, u64 x, u64 w) {
    asm("fma.rn.f32x2 %0, %1, %2, %0;" : "+l"(acc) : "l"(x), "l"(w));
}
__device__ __forceinline__ float hsum2(u64 v) {
    float lo, hi;
    asm("mov.b64 {%0,%1}, %2;" : "=f"(lo), "=f"(hi) : "l"(v));
    return lo + hi;
}
__device__ __forceinline__ u64 pack2(float a, float b) {
    u64 r; asm("mov.b64 %0, {%1,%2};" : "=l"(r) : "f"(a), "f"(b)); return r;
}
__device__ __forceinline__ void unpack2(u64 v, float &lo, float &hi) {
    asm("mov.b64 {%0,%1}, %2;" : "=f"(lo), "=f"(hi) : "l"(v));
}

// ---------------- static scratch ----------------
__device__ float g_wT[4*4*20*160*4];      // wide weights  [l][k][ci4][o(160)][4]
__device__ float g_w1T[4*20*80*4];        // 1x1 weights   [l][ci4][o(80)][4]
__device__ float g_f0T[20*80*4];          // head f0       [ci4][o][4]
__device__ float g_f1T[20*80*4];          // head f1       [ci4][o][4]
__device__ float g_embT[80*512];          // embedding^T   [v][code]
__device__ float g_e2[512];
__device__ float g_edot[512*2];
__device__ float g_qdot[NBATCH*512*2];
__device__ unsigned g_maxkey[NBATCH*2];
__device__ float g_bufA[NBATCH*4096*80];
__device__ float g_bufB[NBATCH*4096*80];
__device__ float g_bufC[NBATCH*4096*80];
__device__ float g_encs[NBATCH*2048*80];
__device__ float g_encq[NBATCH*512*80];

__device__ __forceinline__ unsigned fkey(float f) {
    unsigned u = __float_as_uint(f);
    return (u & 0x80000000u) ? ~u : (u | 0x80000000u);
}
__device__ __forceinline__ float funkey(unsigned k) {
    unsigned u = (k & 0x80000000u) ? (k & 0x7FFFFFFFu) : ~k;
    return __uint_as_float(u);
}

// ---------------- prep ----------------
__global__ void prep_kernel(const float* __restrict__ w_wide,
                            const float* __restrict__ w_1x1,
                            const float* __restrict__ w_f0,
                            const float* __restrict__ w_f1,
                            const float* __restrict__ emb,
                            const float* __restrict__ w_lin) {
    int i = blockIdx.x * blockDim.x + threadIdx.x;
    if (i < 204800) {
        int cc = i & 3; int j = i >> 2;
        int o = j % 160; j /= 160;
        int ci4 = j % 20; j /= 20;
        int k = j % 4; int l = j >> 2;
        g_wT[i] = w_wide[((l*160 + o)*80 + (ci4*4 + cc))*4 + k];
        return;
    }
    i -= 204800;
    if (i < 25600) {
        int cc = i & 3; int j = i >> 2;
        int o = j % 80; j /= 80;
        int ci4 = j % 20; int l = j / 20;
        g_w1T[i] = w_1x1[(l*80 + o)*80 + (ci4*4 + cc)];
        return;
    }
    i -= 25600;
    if (i < 6400) {
        int cc = i & 3; int j = i >> 2;
        int o = j % 80; int ci4 = j / 80;
        g_f0T[i] = w_f0[o*80 + (ci4*4 + cc)];
        return;
    }
    i -= 6400;
    if (i < 6400) {
        int cc = i & 3; int j = i >> 2;
        int o = j % 80; int ci4 = j / 80;
        g_f1T[i] = w_f1[o*80 + (ci4*4 + cc)];
        return;
    }
    i -= 6400;
    if (i < 80*512) {
        int code = i % 512; int v = i / 512;
        g_embT[i] = emb[code*80 + v];
        return;
    }
    i -= 80*512;
    if (i < 512) {
        float s = 0.f, d0 = 0.f, d1 = 0.f;
        for (int v = 0; v < 80; v++) {
            float e = emb[i*80 + v];
            s += e*e;
            d0 += e * w_lin[v];
            d1 += e * w_lin[80 + v];
        }
        g_e2[i] = s; g_edot[i*2] = d0; g_edot[i*2+1] = d1;
        return;
    }
    i -= 512;
    if (i < NBATCH*2) g_maxkey[i] = 0x007FFFFFu;  // key(-inf)
}

// ---------------- fused layer: wide conv + GLU + 1x1 (+res) (+head) ----------------
// block (80,4); 8 time-steps per thread => 32 output times per block.
template<bool RES, bool HEAD>
__global__ void layer_kernel(const float* __restrict__ xS, const float* __restrict__ xQ,
                             float* __restrict__ oS, float* __restrict__ oQ,
                             float* __restrict__ encS, float* __restrict__ encQ,
                             const float4* __restrict__ wT4, const float* __restrict__ bw,
                             const float4* __restrict__ w1, const float* __restrict__ b1,
                             const float4* __restrict__ f0, const float4* __restrict__ f1,
                             const float* __restrict__ bf0, const float* __restrict__ bf1,
                             int TinS, int ToutS, int tilesS,
                             int TinQ, int ToutQ, int stride) {
    __shared__ __align__(16) float4 s4[66*20];     // input tile (also residual source)
    __shared__ __align__(16) float  s_glu[32][80]; // GLU outputs (reused as relu-hidden)
    __shared__ __align__(16) float  s_out[32][80]; // 1x1+res outputs (head input)

    int n = blockIdx.y;
    bool isQ = ((int)blockIdx.x >= tilesS);
    int tile = isQ ? ((int)blockIdx.x - tilesS) : (int)blockIdx.x;
    const float* xin = isQ ? xQ : xS;
    int Tin  = isQ ? TinQ  : TinS;
    int Tout = isQ ? ToutQ : ToutS;
    float* out = isQ ? oQ : oS;
    float* enc = isQ ? encQ : encS;

    int t0 = tile * 32;
    int base_in = t0 * stride;
    int nrows = 31*stride + 4;
    int c = threadIdx.x, tt = threadIdx.y;
    int tid = tt*80 + c;

    // ---- load input tile ----
    const float4* xrow4 = (const float4*)(xin + (size_t)n * Tin * 80);
    for (int idx = tid; idx < nrows*20; idx += 320) {
        int r = idx / 20, q = idx % 20;
        int tg = base_in + r;
        s4[idx] = (tg < Tin) ? xrow4[(size_t)tg*20 + q] : make_float4(0.f,0.f,0.f,0.f);
    }
    __syncthreads();

    // ---- phase 1: wide conv (160ch) + GLU, f32x2 packed over channel pairs ----
    u64 a2[8], g2[8];
    #pragma unroll
    for (int j = 0; j < 8; j++) { a2[j] = 0ull; g2[j] = 0ull; }

    for (int k = 0; k < 4; k++) {
        #pragma unroll 2
        for (int ci4 = 0; ci4 < 20; ci4++) {
            ulonglong2 wa = *(const ulonglong2*)&wT4[(k*20 + ci4)*160 + c];
            ulonglong2 wg = *(const ulonglong2*)&wT4[(k*20 + ci4)*160 + c + 80];
            #pragma unroll
            for (int j = 0; j < 8; j++) {
                int tl = tt*8 + j;
                ulonglong2 xv = *(const ulonglong2*)&s4[(tl*stride + k)*20 + ci4];
                fma2(a2[j], xv.x, wa.x);
                fma2(a2[j], xv.y, wa.y);
                fma2(g2[j], xv.x, wg.x);
                fma2(g2[j], xv.y, wg.y);
            }
        }
    }
    {
        float ba = bw[c], bg = bw[c + 80];
        #pragma unroll
        for (int j = 0; j < 8; j++) {
            float A = hsum2(a2[j]) + ba;
            float G = hsum2(g2[j]) + bg;
            s_glu[tt*8 + j][c] = tanhf(A) * (1.f / (1.f + __expf(-G)));
        }
    }
    __syncthreads();

    // ---- phase 2: 1x1 conv (+ residual from input tile) ----
    u64 acc2[8];
    #pragma unroll
    for (int j = 0; j < 8; j++) acc2[j] = 0ull;
    #pragma unroll 4
    for (int ci4 = 0; ci4 < 20; ci4++) {
        ulonglong2 w = *(const ulonglong2*)&w1[ci4*80 + c];
        #pragma unroll
        for (int j = 0; j < 8; j++) {
            ulonglong2 xv = *(const ulonglong2*)&s_glu[tt*8 + j][ci4*4];
            fma2(acc2[j], xv.x, w.x);
            fma2(acc2[j], xv.y, w.y);
        }
    }
    {
        float bc = b1[c];
        const float* s_in_f = (const float*)s4;
        float* orow = out + (size_t)n * Tout * 80;
        #pragma unroll
        for (int j = 0; j < 8; j++) {
            int jl = tt*8 + j;
            int t = t0 + jl;
            float v = hsum2(acc2[j]) + bc;
            if (RES) v += s_in_f[(jl*stride + 3)*80 + c];
            if (HEAD) {
                s_out[jl][c] = v;
            } else {
                if (t < Tout) orow[(size_t)t*80 + c] = v;
            }
        }
    }

    if (HEAD) {
        __syncthreads();
        // f0 + relu -> s_glu (reused)
        u64 h2[8];
        #pragma unroll
        for (int j = 0; j < 8; j++) h2[j] = 0ull;
        #pragma unroll 4
        for (int ci4 = 0; ci4 < 20; ci4++) {
            ulonglong2 w = *(const ulonglong2*)&f0[ci4*80 + c];
            #pragma unroll
            for (int j = 0; j < 8; j++) {
                ulonglong2 xv = *(const ulonglong2*)&s_out[tt*8 + j][ci4*4];
                fma2(h2[j], xv.x, w.x);
                fma2(h2[j], xv.y, w.y);
            }
        }
        {
            float b0c = bf0[c];
            #pragma unroll
            for (int j = 0; j < 8; j++)
                s_glu[tt*8 + j][c] = fmaxf(hsum2(h2[j]) + b0c, 0.f);
        }
        __syncthreads();
        // f1 -> enc
        u64 o2[8];
        #pragma unroll
        for (int j = 0; j < 8; j++) o2[j] = 0ull;
        #pragma unroll 4
        for (int ci4 = 0; ci4 < 20; ci4++) {
            ulonglong2 w = *(const ulonglong2*)&f1[ci4*80 + c];
            #pragma unroll
            for (int j = 0; j < 8; j++) {
                ulonglong2 xv = *(const ulonglong2*)&s_glu[tt*8 + j][ci4*4];
                fma2(o2[j], xv.x, w.x);
                fma2(o2[j], xv.y, w.y);
            }
        }
        {
            float b1c = bf1[c];
            #pragma unroll
            for (int j = 0; j < 8; j++) {
                int t = t0 + tt*8 + j;
                if (t < Tout) enc[((size_t)n*Tout + t)*80 + c] = hsum2(o2[j]) + b1c;
            }
        }
    }
}

// ---------------- qdot ----------------
__global__ void qdot_kernel(const float* __restrict__ encq, const float* __restrict__ w_lin, int Tq) {
    int i = blockIdx.x * blockDim.x + threadIdx.x;
    if (i >= NBATCH * Tq * 2) return;
    int cch = i & 1; int row = i >> 1;
    float s = 0.f;
    const float* xr = encq + (size_t)row * 80;
    const float* wr = w_lin + cch * 80;
    for (int v = 0; v < 80; v++) s += xr[v] * wr[v];
    g_qdot[i] = s;
}

// ---------------- VQ argmin + fused linear + max reduce ----------------
// 16 rows per block, 128 threads (each owns 4 codes); f32x2 over row pairs.
__global__ void vq_kernel(const float* __restrict__ enc, const float* __restrict__ b_lin,
                          int Ts, int Tq, int Tfill, int totalRows) {
    __shared__ __align__(16) float xsT[80][16];
    __shared__ float sx2[16];
    __shared__ float rd[16][128];
    __shared__ int   ri[16][128];
    int tid = threadIdx.x;
    int rowBase = blockIdx.x * 16;

    for (int idx = tid; idx < 1280; idx += 128) {
        int v = idx >> 4, r = idx & 15;
        int row = rowBase + r;
        xsT[v][r] = (row < totalRows) ? enc[(size_t)row*80 + v] : 0.f;
    }
    __syncthreads();
    if (tid < 16) {
        float s = 0.f;
        for (int v = 0; v < 80; v++) { float x = xsT[v][tid]; s += x*x; }
        sx2[tid] = s;
    }
    __syncthreads();

    u64 xe2[4][8];
    #pragma unroll
    for (int co = 0; co < 4; co++)
        #pragma unroll
        for (int p = 0; p < 8; p++) xe2[co][p] = 0ull;

    #pragma unroll 4
    for (int v = 0; v < 80; v++) {
        ulonglong2 xa = *(const ulonglong2*)&xsT[v][0];
        ulonglong2 xb = *(const ulonglong2*)&xsT[v][4];
        ulonglong2 xc = *(const ulonglong2*)&xsT[v][8];
        ulonglong2 xd = *(const ulonglong2*)&xsT[v][12];
        u64 xr2[8] = {xa.x, xa.y, xb.x, xb.y, xc.x, xc.y, xd.x, xd.y};
        #pragma unroll
        for (int co = 0; co < 4; co++) {
            float ev = g_embT[v*512 + co*128 + tid];
            u64 evv = pack2(ev, ev);
            #pragma unroll
            for (int p = 0; p < 8; p++) fma2(xe2[co][p], xr2[p], evv);
        }
    }

    float bestd[16]; int besti[16];
    #pragma unroll
    for (int r = 0; r < 16; r++) { bestd[r] = 3.4e38f; besti[r] = 0; }
    #pragma unroll
    for (int co = 0; co < 4; co++) {
        int code = co*128 + tid;
        float e2c = g_e2[code];
        #pragma unroll
        for (int p = 0; p < 8; p++) {
            float lo, hi;
            unpack2(xe2[co][p], lo, hi);
            float d0 = sx2[2*p]   - 2.f*lo + e2c;
            float d1 = sx2[2*p+1] - 2.f*hi + e2c;
            if (d0 < bestd[2*p])   { bestd[2*p]   = d0; besti[2*p]   = code; }
            if (d1 < bestd[2*p+1]) { bestd[2*p+1] = d1; besti[2*p+1] = code; }
        }
    }
    #pragma unroll
    for (int r = 0; r < 16; r++) { rd[r][tid] = bestd[r]; ri[r][tid] = besti[r]; }
    __syncthreads();

    for (int s = 64; s > 0; s >>= 1) {
        if (tid < s) {
            #pragma unroll
            for (int r = 0; r < 16; r++) {
                float d2v = rd[r][tid+s]; int i2 = ri[r][tid+s];
                float d1v = rd[r][tid];   int i1 = ri[r][tid];
                if (d2v < d1v || (d2v == d1v && i2 < i1)) { rd[r][tid] = d2v; ri[r][tid] = i2; }
            }
        }
        __syncthreads();
    }

    if (tid < 16) {
        int row = rowBase + tid;
        if (row < totalRows) {
            int n = row / Ts;
            int t = row % Ts;
            int idx = ri[tid][0];
            float q0 = 0.f, q1 = 0.f;
            if (t < Tfill) {
                int tq = t % Tq;
                q0 = g_qdot[((size_t)n*Tq + tq)*2];
                q1 = g_qdot[((size_t)n*Tq + tq)*2 + 1];
            }
            float s0 = q0 + g_edot[idx*2]     + b_lin[0];
            float s1 = q1 + g_edot[idx*2 + 1] + b_lin[1];
            atomicMax(&g_maxkey[n*2],     fkey(s0));
            atomicMax(&g_maxkey[n*2 + 1], fkey(s1));
        }
    }
}

__global__ void final_kernel(float* __restrict__ out) {
    int i = threadIdx.x;
    if (i < NBATCH*2) out[i] = tanhf(funkey(g_maxkey[i]));
}

// ---------------- host orchestration ----------------
extern "C" void kernel_launch(void* const* d_in, const int* in_sizes, int n_in,
                              void* d_out, int out_size) {
    const float* search = (const float*)d_in[0];
    const float* query  = (const float*)d_in[1];
    const float* w_wide = (const float*)d_in[2];
    const float* b_wide = (const float*)d_in[3];
    const float* w_1x1  = (const float*)d_in[4];
    const float* b_1x1  = (const float*)d_in[5];
    const float* w_f0   = (const float*)d_in[6];
    const float* b_f0   = (const float*)d_in[7];
    const float* w_f1   = (const float*)d_in[8];
    const float* b_f1   = (const float*)d_in[9];
    const float* emb    = (const float*)d_in[10];
    const float* w_lin  = (const float*)d_in[11];
    const float* b_lin  = (const float*)d_in[12];

    int Ts = in_sizes[0] / (NBATCH * 80);
    int Tq = in_sizes[1] / (NBATCH * 80);

    float *pA, *pB, *pC, *pEncS, *pEncQ, *pWT, *pW1T, *pF0T, *pF1T;
    cudaGetSymbolAddress((void**)&pA, g_bufA);
    cudaGetSymbolAddress((void**)&pB, g_bufB);
    cudaGetSymbolAddress((void**)&pC, g_bufC);
    cudaGetSymbolAddress((void**)&pEncS, g_encs);
    cudaGetSymbolAddress((void**)&pEncQ, g_encq);
    cudaGetSymbolAddress((void**)&pWT, g_wT);
    cudaGetSymbolAddress((void**)&pW1T, g_w1T);
    cudaGetSymbolAddress((void**)&pF0T, g_f0T);
    cudaGetSymbolAddress((void**)&pF1T, g_f1T);

    int prepTotal = 204800 + 25600 + 6400 + 6400 + 80*512 + 512 + NBATCH*2;
    prep_kernel<<<(prepTotal + 255) / 256, 256>>>(w_wide, w_1x1, w_f0, w_f1, emb, w_lin);

    float* qPing = pC;
    float* qPong = pC + (size_t)NBATCH * 2048 * 80;

    const float* curS = search; const float* curQ = query;
    float* sBufs[2] = { pA, pB };
    float* qBufs[2] = { qPing, qPong };
    int TS = Ts, TQ = Tq;
    int flip = 0;
    int ToutS_final = 0, ToutQ_final = 0;

    for (int l = 0; l < 4; l++) {
        int stride = (l < 2) ? 2 : 1;
        int ToutS = (TS - 4) / stride + 1;
        int ToutQ = (TQ - 4) / stride + 1;
        int tilesS = (ToutS + 31) / 32;
        int tilesQ = (ToutQ + 31) / 32;
        dim3 grid(tilesS + tilesQ, NBATCH), block(80, 4);
        float* outS = sBufs[flip];
        float* outQ = qBufs[flip];
        const float4* wT4 = (const float4*)(pWT + (size_t)l * 4*20*160*4);
        const float4* w14 = (const float4*)(pW1T + (size_t)l * 20*80*4);
        if (l == 0) {
            layer_kernel<false,false><<<grid, block>>>(curS, curQ, outS, outQ, pEncS, pEncQ,
                wT4, b_wide + l*160, w14, b_1x1 + l*80,
                (const float4*)pF0T, (const float4*)pF1T, b_f0, b_f1,
                TS, ToutS, tilesS, TQ, ToutQ, stride);
        } else if (l < 3) {
            layer_kernel<true,false><<<grid, block>>>(curS, curQ, outS, outQ, pEncS, pEncQ,
                wT4, b_wide + l*160, w14, b_1x1 + l*80,
                (const float4*)pF0T, (const float4*)pF1T, b_f0, b_f1,
                TS, ToutS, tilesS, TQ, ToutQ, stride);
        } else {
            layer_kernel<true,true><<<grid, block>>>(curS, curQ, outS, outQ, pEncS, pEncQ,
                wT4, b_wide + l*160, w14, b_1x1 + l*80,
                (const float4*)pF0T, (const float4*)pF1T, b_f0, b_f1,
                TS, ToutS, tilesS, TQ, ToutQ, stride);
        }
        curS = outS; curQ = outQ;
        flip ^= 1;
        TS = ToutS; TQ = ToutQ;
        ToutS_final = ToutS; ToutQ_final = ToutQ;
    }

    int Ts4 = ToutS_final, Tq4 = ToutQ_final;

    qdot_kernel<<<(NBATCH*Tq4*2 + 255) / 256, 256>>>(pEncQ, w_lin, Tq4);

    int sf = Ts4 / Tq4;
    int Tfill = sf * Tq4;
    int totalRows = NBATCH * Ts4;
    vq_kernel<<<(totalRows + 15) / 16, 128>>>(pEncS, b_lin, Ts4, Tq4, Tfill, totalRows);

    final_kernel<<<1, 32>>>((float*)d_out);
}